// round 1
// baseline (speedup 1.0000x reference)
#include <cuda_runtime.h>
#include <cuda_bf16.h>
#include <cstdint>
#include <cstddef>

using bf16 = __nv_bfloat16;
using bf162 = __nv_bfloat162;

constexpr int Bdim = 8, Ldim = 512, Hdim = 768, Odim = 12;
constexpr int Kdim = Hdim;                 // contraction dim for both GEMMs
constexpr float NEGC = 1000000000000.0f;   // 1e12

constexpr int BM = 128, BN = 128, BK = 32, PAD = 8, LDSH = BK + PAD; // 40
constexpr int BUFBYTES = BM * LDSH * 2;    // 10240 bytes per stage buffer

// ---------------- scratch (device globals: no allocation in kernel_launch) ----
__device__ __align__(16) bf16  g_in  [Bdim * Ldim * Hdim];             // [b*L+x][i], bf16 inputs
__device__ __align__(16) bf16  g_w1t [Odim * Hdim * Hdim];             // [n=o*H+j][i], W1 transposed
__device__ __align__(16) bf16  g_U   [(size_t)Bdim * Odim * Ldim * Hdim]; // [((b*O+o)*L+x)][j]
__device__ float g_lina[Bdim * Ldim * Odim];
__device__ float g_linb[Bdim * Ldim * Odim];

// ---------------- small helpers ----------------------------------------------
__device__ __forceinline__ uint32_t s2u(const void* p) {
    return (uint32_t)__cvta_generic_to_shared(p);
}
__device__ __forceinline__ void cp16(uint32_t s, const void* g) {
    asm volatile("cp.async.cg.shared.global [%0], [%1], 16;" :: "r"(s), "l"(g));
}
__device__ __forceinline__ void cp_commit() {
    asm volatile("cp.async.commit_group;");
}
template <int N>
__device__ __forceinline__ void cp_wait() {
    asm volatile("cp.async.wait_group %0;" :: "n"(N));
}

__device__ __forceinline__ void mma_op(float* c, const uint32_t* a, const uint32_t* bq) {
    asm volatile(
        "mma.sync.aligned.m16n8k16.row.col.f32.bf16.bf16.f32 "
        "{%0,%1,%2,%3},{%4,%5,%6,%7},{%8,%9},{%0,%1,%2,%3};"
        : "+f"(c[0]), "+f"(c[1]), "+f"(c[2]), "+f"(c[3])
        : "r"(a[0]), "r"(a[1]), "r"(a[2]), "r"(a[3]), "r"(bq[0]), "r"(bq[1]));
}

// Compute one BK-wide smem K-slab for this warp's 64x32 tile.
__device__ __forceinline__ void mma_tile(float acc[4][4][4],
                                         const bf16 (*As)[LDSH],
                                         const bf16 (*Bs)[LDSH],
                                         int wm, int wn, int lane) {
    int r = lane & 7, sub = lane >> 3;
    #pragma unroll
    for (int kk = 0; kk < BK; kk += 16) {
        uint32_t a[4][4], bq[4][2];
        #pragma unroll
        for (int mt = 0; mt < 4; mt++) {
            uint32_t addr = s2u(&As[wm * 64 + mt * 16 + (sub & 1) * 8 + r][kk + (sub >> 1) * 8]);
            asm volatile("ldmatrix.sync.aligned.m8n8.x4.shared.b16 {%0,%1,%2,%3}, [%4];"
                         : "=r"(a[mt][0]), "=r"(a[mt][1]), "=r"(a[mt][2]), "=r"(a[mt][3])
                         : "r"(addr));
        }
        #pragma unroll
        for (int p = 0; p < 2; p++) {
            // matrices: (n0..n0+7, kk), (n0..n0+7, kk+8), (n0+8.., kk), (n0+8.., kk+8)
            uint32_t addr = s2u(&Bs[wn * 32 + p * 16 + (sub >> 1) * 8 + r][kk + (sub & 1) * 8]);
            uint32_t v0, v1, v2, v3;
            asm volatile("ldmatrix.sync.aligned.m8n8.x4.shared.b16 {%0,%1,%2,%3}, [%4];"
                         : "=r"(v0), "=r"(v1), "=r"(v2), "=r"(v3) : "r"(addr));
            bq[2 * p][0] = v0; bq[2 * p][1] = v1;
            bq[2 * p + 1][0] = v2; bq[2 * p + 1][1] = v3;
        }
        #pragma unroll
        for (int mt = 0; mt < 4; mt++)
            #pragma unroll
            for (int nt = 0; nt < 4; nt++)
                mma_op(acc[mt][nt], a[mt], bq[nt]);
    }
}

// Shared 128x128x768 NT-GEMM mainloop (A row-major K-contig, B row-major-per-N K-contig)
__device__ __forceinline__ void gemm_mainloop(const bf16* __restrict__ Ablk,
                                              const bf16* __restrict__ Bblk,
                                              float acc[4][4][4]) {
    __shared__ __align__(16) bf16 As[2][BM][LDSH];
    __shared__ __align__(16) bf16 Bs[2][BM][LDSH];
    int t = threadIdx.x;
    int lane = t & 31, warp = t >> 5;
    int wm = warp >> 2, wn = warp & 3;
    int kc = t & 3, r0 = t >> 2;  // chunk col (16B units), row 0..63 (second row r0+64)

    const bf16* ag0 = Ablk + (size_t)r0 * Kdim + kc * 8;
    const bf16* ag1 = ag0 + (size_t)64 * Kdim;
    const bf16* bg0 = Bblk + (size_t)r0 * Kdim + kc * 8;
    const bf16* bg1 = bg0 + (size_t)64 * Kdim;
    uint32_t sa0 = s2u(&As[0][r0][kc * 8]);
    uint32_t sa1 = s2u(&As[0][r0 + 64][kc * 8]);
    uint32_t sb0 = s2u(&Bs[0][r0][kc * 8]);
    uint32_t sb1 = s2u(&Bs[0][r0 + 64][kc * 8]);

    cp16(sa0, ag0); cp16(sa1, ag1); cp16(sb0, bg0); cp16(sb1, bg1);
    cp_commit();

    constexpr int KT = Kdim / BK;  // 24
    #pragma unroll 1
    for (int kt = 0; kt < KT; kt++) {
        int buf = kt & 1;
        if (kt + 1 < KT) {
            int nb = buf ^ 1;
            int koff = (kt + 1) * BK;
            cp16(sa0 + nb * BUFBYTES, ag0 + koff);
            cp16(sa1 + nb * BUFBYTES, ag1 + koff);
            cp16(sb0 + nb * BUFBYTES, bg0 + koff);
            cp16(sb1 + nb * BUFBYTES, bg1 + koff);
            cp_commit();
            cp_wait<1>();
        } else {
            cp_wait<0>();
        }
        __syncthreads();
        mma_tile(acc, As[buf], Bs[buf], wm, wn, lane);
        __syncthreads();
    }
}

// ---------------- prep kernels ------------------------------------------------
__global__ void convert_in_kernel(const float* __restrict__ in) {
    int i = (blockIdx.x * blockDim.x + threadIdx.x) * 4;
    float4 v = *reinterpret_cast<const float4*>(in + i);
    *reinterpret_cast<bf162*>(&g_in[i])     = __floats2bfloat162_rn(v.x, v.y);
    *reinterpret_cast<bf162*>(&g_in[i + 2]) = __floats2bfloat162_rn(v.z, v.w);
}

__global__ void transpose_w1_kernel(const float* __restrict__ w1) {
    __shared__ float tile[32][33];
    int n0 = blockIdx.x * 32, i0 = blockIdx.y * 32;
    int tx = threadIdx.x, ty = threadIdx.y;
    #pragma unroll
    for (int k = 0; k < 32; k += 8)
        tile[ty + k][tx] = w1[(size_t)(i0 + ty + k) * (Odim * Hdim) + n0 + tx];
    __syncthreads();
    #pragma unroll
    for (int k = 0; k < 32; k += 8)
        g_w1t[(size_t)(n0 + ty + k) * Hdim + i0 + tx] = __float2bfloat16(tile[tx][ty + k]);
}

__global__ void lin_kernel(const float* __restrict__ in, const float* __restrict__ w2) {
    int row = blockIdx.x;                       // b*L + x
    int o = threadIdx.x >> 5, lane = threadIdx.x & 31;  // 12 warps = 12 outputs
    const float* x = in + (size_t)row * Hdim;
    float sa = 0.f, sb = 0.f;
    for (int i = lane; i < Hdim; i += 32) {
        float v = x[i];
        sa += v * w2[i * Odim + o];
        sb += v * w2[(Hdim + i) * Odim + o];
    }
    #pragma unroll
    for (int off = 16; off; off >>= 1) {
        sa += __shfl_xor_sync(0xffffffffu, sa, off);
        sb += __shfl_xor_sync(0xffffffffu, sb, off);
    }
    if (lane == 0) { g_lina[row * Odim + o] = sa; g_linb[row * Odim + o] = sb; }
}

// ---------------- GEMM 1: U = in @ W1  (M=4096, N=9216, K=768) ---------------
__global__ __launch_bounds__(256) void gemm1_kernel() {
    const bf16* Ablk = g_in  + (size_t)blockIdx.y * BM * Kdim;
    const bf16* Bblk = g_w1t + (size_t)blockIdx.x * BN * Kdim;
    float acc[4][4][4];
    #pragma unroll
    for (int i = 0; i < 4; i++)
        #pragma unroll
        for (int j = 0; j < 4; j++)
            #pragma unroll
            for (int e = 0; e < 4; e++) acc[i][j][e] = 0.f;
    gemm_mainloop(Ablk, Bblk, acc);

    int t = threadIdx.x, lane = t & 31, warp = t >> 5;
    int wm = warp >> 2, wn = warp & 3;
    int g = lane >> 2, tig = lane & 3;
    int o  = (blockIdx.x * BN) / Hdim;       // 128 | 768, so no straddle
    int jb = blockIdx.x * BN - o * Hdim;
    #pragma unroll
    for (int mt = 0; mt < 4; mt++) {
        int R = blockIdx.y * BM + wm * 64 + mt * 16 + g;
        int b = R >> 9, x = R & (Ldim - 1);
        #pragma unroll
        for (int nt = 0; nt < 4; nt++) {
            int j = jb + wn * 32 + nt * 8 + 2 * tig;
            size_t base = ((size_t)(b * Odim + o) * Ldim + x) * Hdim + j;
            *reinterpret_cast<bf162*>(&g_U[base]) =
                __floats2bfloat162_rn(acc[mt][nt][0], acc[mt][nt][1]);
            *reinterpret_cast<bf162*>(&g_U[base + (size_t)8 * Hdim]) =
                __floats2bfloat162_rn(acc[mt][nt][2], acc[mt][nt][3]);
        }
    }
}

// ------- GEMM 2: logits[b,o,x,y] = U[b,o,x,:]·in[b,y,:] + lin + bias, mask+tril
__global__ __launch_bounds__(256) void gemm2_kernel(const float* __restrict__ w2,
                                                    const int* __restrict__ mask,
                                                    float* __restrict__ out) {
    int z = blockIdx.z;                 // b*O + o
    int b = z / Odim, o = z - b * Odim;
    const bf16* Ablk = g_U  + ((size_t)z * Ldim + blockIdx.y * BM) * Hdim;
    const bf16* Bblk = g_in + ((size_t)b * Ldim + blockIdx.x * BN) * Hdim;
    float acc[4][4][4];
    #pragma unroll
    for (int i = 0; i < 4; i++)
        #pragma unroll
        for (int j = 0; j < 4; j++)
            #pragma unroll
            for (int e = 0; e < 4; e++) acc[i][j][e] = 0.f;
    gemm_mainloop(Ablk, Bblk, acc);

    int t = threadIdx.x, lane = t & 31, warp = t >> 5;
    int wm = warp >> 2, wn = warp & 3;
    int g = lane >> 2, tig = lane & 3;
    float bias = w2[2 * Hdim * Odim + o];
    int x0 = blockIdx.y * BM + wm * 64;
    int y0 = blockIdx.x * BN + wn * 32;

    // column-side precompute (y, mask_y, linb)
    float lb[4][2]; int my[4][2]; int yv[4];
    #pragma unroll
    for (int nt = 0; nt < 4; nt++) {
        int y = y0 + nt * 8 + 2 * tig;
        yv[nt] = y;
        #pragma unroll
        for (int e = 0; e < 2; e++) {
            my[nt][e] = mask[b * Ldim + y + e];
            lb[nt][e] = g_linb[(b * Ldim + y + e) * Odim + o];
        }
    }
    #pragma unroll
    for (int mt = 0; mt < 4; mt++) {
        #pragma unroll
        for (int h = 0; h < 2; h++) {
            int x = x0 + mt * 16 + g + h * 8;
            int mx = mask[b * Ldim + x];
            float ra = g_lina[(b * Ldim + x) * Odim + o] + bias;
            float* orow = out + ((size_t)z * Ldim + x) * Ldim;
            #pragma unroll
            for (int nt = 0; nt < 4; nt++) {
                int y = yv[nt];
                float2 v;
                v.x = (mx && my[nt][0]) ? (acc[mt][nt][h * 2 + 0] + ra + lb[nt][0]) : -NEGC;
                v.y = (mx && my[nt][1]) ? (acc[mt][nt][h * 2 + 1] + ra + lb[nt][1]) : -NEGC;
                if (y     < x) v.x -= NEGC;   // strictly-lower triangle flood
                if (y + 1 < x) v.y -= NEGC;
                *reinterpret_cast<float2*>(orow + y) = v;
            }
        }
    }
}

// ---------------- launch ------------------------------------------------------
extern "C" void kernel_launch(void* const* d_in, const int* in_sizes, int n_in,
                              void* d_out, int out_size) {
    (void)out_size;
    const float* inputs = nullptr; const float* w1 = nullptr;
    const float* w2 = nullptr;     const int* mask = nullptr;
    for (int i = 0; i < n_in; i++) {
        int s = in_sizes[i];
        if      (s == Bdim * Ldim * Hdim)   inputs = (const float*)d_in[i];
        else if (s == Hdim * Odim * Hdim)   w1     = (const float*)d_in[i];
        else if (s == (2 * Hdim + 1) * Odim) w2    = (const float*)d_in[i];
        else if (s == Bdim * Ldim)          mask   = (const int*)d_in[i];
    }
    float* out = (float*)d_out;

    convert_in_kernel<<<(Bdim * Ldim * Hdim) / 1024, 256>>>(inputs);
    transpose_w1_kernel<<<dim3((Odim * Hdim) / 32, Hdim / 32), dim3(32, 8)>>>(w1);
    lin_kernel<<<Bdim * Ldim, 384>>>(inputs, w2);
    gemm1_kernel<<<dim3((Odim * Hdim) / BN, (Bdim * Ldim) / BM), 256>>>();
    gemm2_kernel<<<dim3(Ldim / BN, Ldim / BM, Bdim * Odim), 256>>>(w2, mask, out);
}